// round 3
// baseline (speedup 1.0000x reference)
#include <cuda_runtime.h>
#include <cstdint>

#define SEQ    2048
#define DIM    4096
#define NHEADS 32
#define NKV    8
#define HD     128
#define KVDIM  (NKV*HD)   // 1024

#define BM 128
#define BN 128
#define BK 16
#define AST 20    // As row stride (floats): (20m+k)%32 is a permutation -> conflict-free
#define BST 136   // Bs row stride (floats): (8k+n)%32 is a permutation  -> conflict-free

// Scratch (device globals: the sanctioned no-alloc workaround)
__device__ float g_q[(size_t)SEQ * DIM];
__device__ float g_k[(size_t)SEQ * KVDIM];
__device__ float g_v[(size_t)SEQ * KVDIM];
__device__ float g_attn[(size_t)SEQ * DIM];
__device__ float g_scores[(size_t)NHEADS * SEQ * SEQ];   // 512 MB

__device__ __forceinline__ float tf32r(float x) {
    unsigned u;
    asm("cvt.rna.tf32.f32 %0, %1;" : "=r"(u) : "f"(x));
    return __uint_as_float(u);
}

// C = A @ B(t) with tf32 mma.sync. A row-major [M,K] (lda).
// BT==0: B row-major [K,N] (ldb).  BT==1: B row-major [N,K] (ldb) i.e. C = A @ B^T.
// Per-z offsets: A += z*sA, B += (z/bdiv)*sB, C += z*sC.
// causal: scale then mask cols > row with -1e30; fully-masked tiles skip compute.
// klim: truncate K to (block_row+1)*BM (causal PV optimization; P is 0 beyond).
template<int BT>
__global__ void __launch_bounds__(256, 2)
gemm_tf32(const float* __restrict__ A, const float* __restrict__ B, float* __restrict__ C,
          int K, int lda, int ldb, int ldc,
          long sA, long sB, long sC, int bdiv,
          float scale, int causal, int klim)
{
    __shared__ float As[2][BM * AST];
    __shared__ float Bs[2][BK * BST];

    int z = blockIdx.z;
    A += (long)z * sA;
    B += (long)(z / bdiv) * sB;
    C += (long)z * sC;

    int bm = blockIdx.y, bn = blockIdx.x;
    int m0 = bm * BM, n0 = bn * BN;
    int tid  = threadIdx.x;
    int lane = tid & 31, warp = tid >> 5;
    int wm = warp >> 2, wn = warp & 3;   // 2 x 4 warp grid -> 64 x 32 warp tile
    int g  = lane >> 2, tg = lane & 3;

    // Fully-masked causal tile: fill with -1e30 and exit (no MMA work).
    if (causal && n0 >= m0 + BM) {
        #pragma unroll
        for (int im = 0; im < 4; im++) {
            int r0 = m0 + wm * 64 + im * 16 + g;
            #pragma unroll
            for (int in = 0; in < 4; in++) {
                int c = n0 + wn * 32 + in * 8 + 2 * tg;
                float2 mv = make_float2(-1e30f, -1e30f);
                *(float2*)&C[(long)r0 * ldc + c]       = mv;
                *(float2*)&C[(long)(r0 + 8) * ldc + c] = mv;
            }
        }
        return;
    }

    int Keff = K;
    if (klim) { int lim = m0 + BM; if (lim < Keff) Keff = lim; }
    int nkt = Keff / BK;

    // Global->shared load mapping (8 consecutive floats per thread = 2 float4)
    int rowA = tid >> 1, colA = (tid & 1) * 8;
    int rowB, colB;
    if (BT == 0) { rowB = tid >> 4; colB = (tid & 15) * 8; }
    else         { rowB = tid >> 1; colB = (tid & 1)  * 8; }

    const float* Ab = A + (long)(m0 + rowA) * lda + colA;
    const float* Bb = (BT == 0) ? (B + (long)rowB * ldb + n0 + colB)
                                : (B + (long)(n0 + rowB) * ldb + colB);

    float acc[4][4][4];
    #pragma unroll
    for (int a = 0; a < 4; a++)
        #pragma unroll
        for (int b = 0; b < 4; b++)
            #pragma unroll
            for (int c = 0; c < 4; c++) acc[a][b][c] = 0.f;

    auto stores = [&](int buf, float4 a0, float4 a1, float4 b0, float4 b1) {
        float* as = &As[buf][rowA * AST + colA];
        as[0] = tf32r(a0.x); as[1] = tf32r(a0.y); as[2] = tf32r(a0.z); as[3] = tf32r(a0.w);
        as[4] = tf32r(a1.x); as[5] = tf32r(a1.y); as[6] = tf32r(a1.z); as[7] = tf32r(a1.w);
        if (BT == 0) {
            float* bs = &Bs[buf][rowB * BST + colB];
            bs[0] = tf32r(b0.x); bs[1] = tf32r(b0.y); bs[2] = tf32r(b0.z); bs[3] = tf32r(b0.w);
            bs[4] = tf32r(b1.x); bs[5] = tf32r(b1.y); bs[6] = tf32r(b1.z); bs[7] = tf32r(b1.w);
        } else {  // transpose into [k][n]
            float* bs = &Bs[buf][colB * BST + rowB];
            bs[0 * BST] = tf32r(b0.x); bs[1 * BST] = tf32r(b0.y);
            bs[2 * BST] = tf32r(b0.z); bs[3 * BST] = tf32r(b0.w);
            bs[4 * BST] = tf32r(b1.x); bs[5 * BST] = tf32r(b1.y);
            bs[6 * BST] = tf32r(b1.z); bs[7 * BST] = tf32r(b1.w);
        }
    };

    float4 pa0, pa1, pb0, pb1;
    pa0 = *reinterpret_cast<const float4*>(Ab);
    pa1 = *reinterpret_cast<const float4*>(Ab + 4);
    pb0 = *reinterpret_cast<const float4*>(Bb);
    pb1 = *reinterpret_cast<const float4*>(Bb + 4);
    stores(0, pa0, pa1, pb0, pb1);
    __syncthreads();

    for (int kt = 0; kt < nkt; ++kt) {
        int cur = kt & 1;
        bool pf = (kt + 1 < nkt);
        if (pf) {
            const float* Ap = Ab + (kt + 1) * BK;
            pa0 = *reinterpret_cast<const float4*>(Ap);
            pa1 = *reinterpret_cast<const float4*>(Ap + 4);
            const float* Bp = (BT == 0) ? (Bb + (long)(kt + 1) * BK * ldb)
                                        : (Bb + (kt + 1) * BK);
            pb0 = *reinterpret_cast<const float4*>(Bp);
            pb1 = *reinterpret_cast<const float4*>(Bp + 4);
        }
        const float* as = As[cur];
        const float* bs = Bs[cur];
        #pragma unroll
        for (int kk = 0; kk < BK; kk += 8) {
            unsigned af[4][4], bf[4][2];
            #pragma unroll
            for (int im = 0; im < 4; im++) {
                int m = wm * 64 + im * 16;
                af[im][0] = __float_as_uint(as[(m + g    ) * AST + kk + tg    ]);
                af[im][1] = __float_as_uint(as[(m + g + 8) * AST + kk + tg    ]);
                af[im][2] = __float_as_uint(as[(m + g    ) * AST + kk + tg + 4]);
                af[im][3] = __float_as_uint(as[(m + g + 8) * AST + kk + tg + 4]);
            }
            #pragma unroll
            for (int in = 0; in < 4; in++) {
                int n = wn * 32 + in * 8;
                bf[in][0] = __float_as_uint(bs[(kk + tg    ) * BST + n + g]);
                bf[in][1] = __float_as_uint(bs[(kk + tg + 4) * BST + n + g]);
            }
            #pragma unroll
            for (int im = 0; im < 4; im++)
                #pragma unroll
                for (int in = 0; in < 4; in++)
                    asm volatile(
                        "mma.sync.aligned.m16n8k8.row.col.f32.tf32.tf32.f32 "
                        "{%0,%1,%2,%3}, {%4,%5,%6,%7}, {%8,%9}, {%0,%1,%2,%3};"
                        : "+f"(acc[im][in][0]), "+f"(acc[im][in][1]),
                          "+f"(acc[im][in][2]), "+f"(acc[im][in][3])
                        : "r"(af[im][0]), "r"(af[im][1]), "r"(af[im][2]), "r"(af[im][3]),
                          "r"(bf[in][0]), "r"(bf[in][1]));
        }
        if (pf) stores(cur ^ 1, pa0, pa1, pb0, pb1);
        __syncthreads();
    }

    // Epilogue
    #pragma unroll
    for (int im = 0; im < 4; im++) {
        int r0 = m0 + wm * 64 + im * 16 + g;
        #pragma unroll
        for (int in = 0; in < 4; in++) {
            int c = n0 + wn * 32 + in * 8 + 2 * tg;
            float v0 = acc[im][in][0] * scale, v1 = acc[im][in][1] * scale;
            float v2 = acc[im][in][2] * scale, v3 = acc[im][in][3] * scale;
            if (causal) {
                if (c     > r0    ) v0 = -1e30f;
                if (c + 1 > r0    ) v1 = -1e30f;
                if (c     > r0 + 8) v2 = -1e30f;
                if (c + 1 > r0 + 8) v3 = -1e30f;
            }
            *(float2*)&C[(long)r0 * ldc + c]       = make_float2(v0, v1);
            *(float2*)&C[(long)(r0 + 8) * ldc + c] = make_float2(v2, v3);
        }
    }
}

// In-place RoPE on Q [SEQ, 32, 128] and K [SEQ, 8, 128].
__global__ void rope_kernel(float* __restrict__ q, float* __restrict__ k,
                            const float* __restrict__ f)
{
    int idx = blockIdx.x * blockDim.x + threadIdx.x;
    const int TOT = SEQ * (NHEADS + NKV) * (HD / 2);
    if (idx >= TOT) return;
    int j = idx & 63;
    int h = (idx >> 6) % (NHEADS + NKV);
    int s = idx / (64 * (NHEADS + NKV));
    float c = f[s * HD + 2 * j];
    float d = f[s * HD + 2 * j + 1];
    float* base;
    if (h < NHEADS) base = q + (long)s * DIM   + h * HD          + 2 * j;
    else            base = k + (long)s * KVDIM + (h - NHEADS) * HD + 2 * j;
    float a = base[0], b = base[1];
    base[0] = a * c - b * d;
    base[1] = a * d + b * c;
}

// Row softmax over L entries (masked entries are -1e30 -> exp == 0). One block / row.
__global__ void softmax_rows(float* __restrict__ sc, int L)
{
    long row = blockIdx.x;
    float* p = sc + row * (long)L;
    int tid = threadIdx.x;
    __shared__ float sm1[8], sm2[8];

    float mx = -3.0e38f;
    for (int i = tid; i < L; i += 256) mx = fmaxf(mx, p[i]);
    #pragma unroll
    for (int o = 16; o > 0; o >>= 1) mx = fmaxf(mx, __shfl_xor_sync(0xffffffffu, mx, o));
    if ((tid & 31) == 0) sm1[tid >> 5] = mx;
    __syncthreads();
    mx = sm1[0];
    #pragma unroll
    for (int i = 1; i < 8; i++) mx = fmaxf(mx, sm1[i]);

    float s = 0.f;
    for (int i = tid; i < L; i += 256) {
        float e = __expf(p[i] - mx);
        p[i] = e;
        s += e;
    }
    #pragma unroll
    for (int o = 16; o > 0; o >>= 1) s += __shfl_xor_sync(0xffffffffu, s, o);
    if ((tid & 31) == 0) sm2[tid >> 5] = s;
    __syncthreads();
    float tot = 0.f;
    #pragma unroll
    for (int i = 0; i < 8; i++) tot += sm2[i];
    float inv = 1.0f / tot;
    for (int i = tid; i < L; i += 256) p[i] *= inv;
}

extern "C" void kernel_launch(void* const* d_in, const int* in_sizes, int n_in,
                              void* d_out, int out_size)
{
    const float* x  = (const float*)d_in[0];
    // d_in[1] = cache_kv (unused: start_pos=0, L=SEQ so cache contents never matter)
    const float* fr = (const float*)d_in[2];
    const float* wq = (const float*)d_in[3];
    const float* wk = (const float*)d_in[4];
    const float* wv = (const float*)d_in[5];
    const float* wo = (const float*)d_in[6];
    float* out = (float*)d_out;

    float *q, *k, *v, *attn, *sc;
    cudaGetSymbolAddress((void**)&q,    g_q);
    cudaGetSymbolAddress((void**)&k,    g_k);
    cudaGetSymbolAddress((void**)&v,    g_v);
    cudaGetSymbolAddress((void**)&attn, g_attn);
    cudaGetSymbolAddress((void**)&sc,   g_scores);

    dim3 thr(256);
    const float rs = 0.08838834764831845f;  // 1/sqrt(128)

    // Projections: Q, K, V
    gemm_tf32<0><<<dim3(DIM / BN,   SEQ / BM, 1), thr>>>(x, wq, q, DIM, DIM, DIM,   DIM,
                                                         0, 0, 0, 1, 1.f, 0, 0);
    gemm_tf32<0><<<dim3(KVDIM / BN, SEQ / BM, 1), thr>>>(x, wk, k, DIM, DIM, KVDIM, KVDIM,
                                                         0, 0, 0, 1, 1.f, 0, 0);
    gemm_tf32<0><<<dim3(KVDIM / BN, SEQ / BM, 1), thr>>>(x, wv, v, DIM, DIM, KVDIM, KVDIM,
                                                         0, 0, 0, 1, 1.f, 0, 0);

    // RoPE on Q and K
    rope_kernel<<<SEQ * (NHEADS + NKV) * (HD / 2) / 256, 256>>>(q, k, fr);

    // scores[h] = (Q_h @ K_{h/4}^T) * rs, causal-masked
    gemm_tf32<1><<<dim3(SEQ / BN, SEQ / BM, NHEADS), thr>>>(q, k, sc, HD, DIM, KVDIM, SEQ,
                                                            (long)HD, (long)HD,
                                                            (long)SEQ * SEQ, 4, rs, 1, 0);

    // softmax over each of the 32*2048 rows
    softmax_rows<<<NHEADS * SEQ, 256>>>(sc, SEQ);

    // attn[h] = P_h @ V_{h/4}  (K-loop truncated at causal boundary)
    gemm_tf32<0><<<dim3(HD / BN, SEQ / BM, NHEADS), thr>>>(sc, v, attn, SEQ, SEQ, KVDIM, DIM,
                                                           (long)SEQ * SEQ, (long)HD,
                                                           (long)HD, 4, 1.f, 0, 1);

    // out = attn @ wo
    gemm_tf32<0><<<dim3(DIM / BN, SEQ / BM, 1), thr>>>(attn, wo, out, DIM, DIM, DIM, DIM,
                                                       0, 0, 0, 1, 1.f, 0, 0);
}

// round 8
// speedup vs baseline: 1.0136x; 1.0136x over previous
#include <cuda_runtime.h>
#include <cstdint>

#define SEQ    2048
#define DIM    4096
#define NHEADS 32
#define NKV    8
#define HD     128
#define KVDIM  1024

#define BMT 128
#define BNT 128
#define BKT 32
#define NSTAGE 3

// A tile: 128 rows x 32 k-floats, row stride 36 floats (144B) -> 18432 B/stage
#define ASTF   36
#define ASTAGE 18432
// B tile (BT==1, [n][k]): same as A
#define BSTAGE1 18432
// B tile (BT==0, [k][n]): 32 k-rows x 128 n-floats, row stride 136 floats (544B)
#define BSTNF   136
#define BSTAGE0 17408

#define SMEM0 (NSTAGE*ASTAGE + NSTAGE*BSTAGE0)   // 107520
#define SMEM1 (NSTAGE*ASTAGE + NSTAGE*BSTAGE1)   // 110592

// ---- scratch (device globals: sanctioned no-alloc workaround) ----
__device__ float g_xr [(size_t)SEQ * DIM];
__device__ float g_wqr[(size_t)DIM * DIM];
__device__ float g_wkr[(size_t)DIM * KVDIM];
__device__ float g_wvr[(size_t)DIM * KVDIM];
__device__ float g_wor[(size_t)DIM * DIM];
__device__ float g_q  [(size_t)SEQ * DIM];
__device__ float g_k  [(size_t)SEQ * KVDIM];
__device__ float g_v  [(size_t)SEQ * KVDIM];
__device__ float g_attn[(size_t)SEQ * DIM];
__device__ float g_scores[(size_t)NHEADS * SEQ * SEQ];

static __device__ __forceinline__ float tf32r(float x) {
    unsigned u;
    asm("cvt.rna.tf32.f32 %0, %1;" : "=r"(u) : "f"(x));
    return __uint_as_float(u);
}
static __device__ __forceinline__ uint32_t smem_u32(const void* p) {
    uint32_t a;
    asm("{ .reg .u64 t; cvta.to.shared.u64 t, %1; cvt.u32.u64 %0, t; }" : "=r"(a) : "l"(p));
    return a;
}
static __device__ __forceinline__ void cp16(uint32_t s, const float* g) {
    asm volatile("cp.async.cg.shared.global [%0], [%1], 16;" :: "r"(s), "l"(g));
}
static __device__ __forceinline__ void cp_commit() {
    asm volatile("cp.async.commit_group;" ::: "memory");
}
template<int N> static __device__ __forceinline__ void cp_wait() {
    asm volatile("cp.async.wait_group %0;" :: "n"(N) : "memory");
}

// C[M,N] = (A[M,K] @ B^T) * scale via mma.sync tf32, cp.async 3-stage pipeline.
// All operands MUST be pre-rounded to tf32 (RNA) — MMA truncation is then exact.
// BT==0: B is [K,N] row-major (ldb). BT==1: B is [N,K] row-major (ldb).
// z-batch: A += z*sA, B += (z/bdiv)*sB, C += z*sC.
// causal: mask col>row with -1e30; fully-masked tiles write NOTHING (never read).
// klim: truncate K at m0+BMT (causal PV). rnd: round epilogue stores to tf32.
template<int BT>
__global__ void __launch_bounds__(256, 2)
gemm_cp(const float* __restrict__ A, const float* __restrict__ B, float* __restrict__ C,
        int K, int lda, int ldb, int ldc,
        long sA, long sB, long sC, int bdiv,
        float scale, int causal, int klim, int rnd)
{
    extern __shared__ char smem[];
    const int tid  = threadIdx.x;
    const int lane = tid & 31, warp = tid >> 5;
    const int m0 = blockIdx.y * BMT, n0 = blockIdx.x * BNT;
    if (causal && n0 >= m0 + BMT) return;   // fully masked: softmax/PV never read it

    const int z = blockIdx.z;
    A += (long)z * sA;
    B += (long)(z / bdiv) * sB;
    C += (long)z * sC;

    int Keff = K;
    if (klim) { int lim = m0 + BMT; if (lim < Keff) Keff = lim; }
    const int nkt = Keff / BKT;   // always >= 2 here

    const uint32_t sbA = smem_u32(smem);
    const uint32_t sbB = sbA + NSTAGE * ASTAGE;

    // ---- producers ----
    // A: thread -> (row tid>>1, 16-float half (tid&1)); 4x cp.async 16B
    const int arow = tid >> 1, ahalf = tid & 1;
    const float*  Agp = A + (long)(m0 + arow) * lda + ahalf * 16;
    const uint32_t AsmO = sbA + (uint32_t)(arow * 144 + ahalf * 64);
    // B
    const float*  Bgp;
    uint32_t BsmO;
    if (BT == 1) {
        Bgp  = B + (long)(n0 + arow) * ldb + ahalf * 16;
        BsmO = sbB + (uint32_t)(arow * 144 + ahalf * 64);
    } else {
        const int brow = tid >> 3, b8 = tid & 7;
        Bgp  = B + (long)brow * ldb + n0 + b8 * 16;
        BsmO = sbB + (uint32_t)(brow * 544 + b8 * 64);
    }

    auto issue = [&](int kt, int st) {
        {
            const float*  g = Agp + kt * BKT;
            const uint32_t s = AsmO + st * ASTAGE;
            #pragma unroll
            for (int q = 0; q < 4; q++) cp16(s + q * 16, g + q * 4);
        }
        if (BT == 1) {
            const float*  g = Bgp + kt * BKT;
            const uint32_t s = BsmO + st * BSTAGE1;
            #pragma unroll
            for (int q = 0; q < 4; q++) cp16(s + q * 16, g + q * 4);
        } else {
            const float*  g = Bgp + (long)kt * BKT * ldb;
            const uint32_t s = BsmO + st * BSTAGE0;
            #pragma unroll
            for (int q = 0; q < 4; q++) cp16(s + q * 16, g + q * 4);
        }
    };

    // ---- consumer fragment mapping ----
    const int wm = warp >> 2, wn = warp & 3;    // 2x4 warps -> 64x32 warp tile
    const int g  = lane >> 2, tg = lane & 3;

    float acc[4][4][4];
    #pragma unroll
    for (int a = 0; a < 4; a++)
        #pragma unroll
        for (int b = 0; b < 4; b++)
            #pragma unroll
            for (int c = 0; c < 4; c++) acc[a][b][c] = 0.f;

    issue(0, 0); cp_commit();
    issue(1, 1); cp_commit();

    int st = 0, pst = 2;
    for (int kt = 0; kt < nkt; kt++) {
        cp_wait<1>();
        __syncthreads();
        if (kt + 2 < nkt) issue(kt + 2, pst);
        cp_commit();

        const float* as = (const float*)(smem + st * ASTAGE);
        const float* bs = (const float*)(smem + NSTAGE * ASTAGE +
                                         st * (BT ? BSTAGE1 : BSTAGE0));
        #pragma unroll
        for (int kk = 0; kk < BKT; kk += 8) {
            unsigned af[4][4], bf[4][2];
            #pragma unroll
            for (int im = 0; im < 4; im++) {
                const int m = wm * 64 + im * 16;
                af[im][0] = __float_as_uint(as[(m + g    ) * ASTF + kk + tg    ]);
                af[im][1] = __float_as_uint(as[(m + g + 8) * ASTF + kk + tg    ]);
                af[im][2] = __float_as_uint(as[(m + g    ) * ASTF + kk + tg + 4]);
                af[im][3] = __float_as_uint(as[(m + g + 8) * ASTF + kk + tg + 4]);
            }
            #pragma unroll
            for (int in = 0; in < 4; in++) {
                const int n = wn * 32 + in * 8;
                if (BT == 1) {
                    bf[in][0] = __float_as_uint(bs[(n + g) * ASTF + kk + tg    ]);
                    bf[in][1] = __float_as_uint(bs[(n + g) * ASTF + kk + tg + 4]);
                } else {
                    bf[in][0] = __float_as_uint(bs[(kk + tg    ) * BSTNF + n + g]);
                    bf[in][1] = __float_as_uint(bs[(kk + tg + 4) * BSTNF + n + g]);
                }
            }
            #pragma unroll
            for (int im = 0; im < 4; im++)
                #pragma unroll
                for (int in = 0; in < 4; in++)
                    asm volatile(
                        "mma.sync.aligned.m16n8k8.row.col.f32.tf32.tf32.f32 "
                        "{%0,%1,%2,%3}, {%4,%5,%6,%7}, {%8,%9}, {%0,%1,%2,%3};"
                        : "+f"(acc[im][in][0]), "+f"(acc[im][in][1]),
                          "+f"(acc[im][in][2]), "+f"(acc[im][in][3])
                        : "r"(af[im][0]), "r"(af[im][1]), "r"(af[im][2]), "r"(af[im][3]),
                          "r"(bf[in][0]), "r"(bf[in][1]));
        }
        st  = (st  == NSTAGE - 1) ? 0 : st + 1;
        pst = (pst == NSTAGE - 1) ? 0 : pst + 1;
    }

    // epilogue (register accs -> C)
    #pragma unroll
    for (int im = 0; im < 4; im++) {
        const int r0 = m0 + wm * 64 + im * 16 + g;
        #pragma unroll
        for (int in = 0; in < 4; in++) {
            const int c = n0 + wn * 32 + in * 8 + 2 * tg;
            float v0 = acc[im][in][0] * scale, v1 = acc[im][in][1] * scale;
            float v2 = acc[im][in][2] * scale, v3 = acc[im][in][3] * scale;
            if (causal) {
                if (c     > r0    ) v0 = -1e30f;
                if (c + 1 > r0    ) v1 = -1e30f;
                if (c     > r0 + 8) v2 = -1e30f;
                if (c + 1 > r0 + 8) v3 = -1e30f;
            }
            if (rnd) {
                v0 = tf32r(v0); v1 = tf32r(v1); v2 = tf32r(v2); v3 = tf32r(v3);
            }
            *(float2*)&C[(long)r0 * ldc + c]       = make_float2(v0, v1);
            *(float2*)&C[(long)(r0 + 8) * ldc + c] = make_float2(v2, v3);
        }
    }
}

// Rounded copy: dst = tf32_rna(src), vectorized.
__global__ void round_copy(const float4* __restrict__ in, float4* __restrict__ out, long n4)
{
    long i = (long)blockIdx.x * blockDim.x + threadIdx.x;
    if (i >= n4) return;
    float4 v = in[i];
    out[i] = make_float4(tf32r(v.x), tf32r(v.y), tf32r(v.z), tf32r(v.w));
}

// In-place RoPE on Q [SEQ,32,128] and K [SEQ,8,128]; outputs tf32-rounded.
__global__ void rope_kernel(float* __restrict__ q, float* __restrict__ k,
                            const float* __restrict__ f)
{
    int idx = blockIdx.x * blockDim.x + threadIdx.x;
    const int TOT = SEQ * (NHEADS + NKV) * (HD / 2);
    if (idx >= TOT) return;
    int j = idx & 63;
    int h = (idx >> 6) % (NHEADS + NKV);
    int s = idx / (64 * (NHEADS + NKV));
    float c = f[s * HD + 2 * j];
    float d = f[s * HD + 2 * j + 1];
    float* base;
    if (h < NHEADS) base = q + (long)s * DIM   + h * HD            + 2 * j;
    else            base = k + (long)s * KVDIM + (h - NHEADS) * HD + 2 * j;
    float a = base[0], b = base[1];
    base[0] = tf32r(a * c - b * d);
    base[1] = tf32r(a * d + b * c);
}

// Row softmax truncated at the 128-aligned causal boundary Lr; rounded output.
__global__ void softmax_rows(float* __restrict__ sc)
{
    const long row = blockIdx.x;             // h*SEQ + i
    const int  i   = (int)(row % SEQ);
    const int  Lr  = ((i >> 7) + 1) << 7;
    float* p = sc + row * (long)SEQ;
    const int tid = threadIdx.x;
    __shared__ float sm1[8], sm2[8];

    float mx = -3.0e38f;
    for (int t = tid; t < Lr; t += 256) mx = fmaxf(mx, p[t]);
    #pragma unroll
    for (int o = 16; o > 0; o >>= 1) mx = fmaxf(mx, __shfl_xor_sync(0xffffffffu, mx, o));
    if ((tid & 31) == 0) sm1[tid >> 5] = mx;
    __syncthreads();
    mx = sm1[0];
    #pragma unroll
    for (int a = 1; a < 8; a++) mx = fmaxf(mx, sm1[a]);

    float s = 0.f;
    for (int t = tid; t < Lr; t += 256) {
        float e = __expf(p[t] - mx);
        p[t] = e;
        s += e;
    }
    #pragma unroll
    for (int o = 16; o > 0; o >>= 1) s += __shfl_xor_sync(0xffffffffu, s, o);
    if ((tid & 31) == 0) sm2[tid >> 5] = s;
    __syncthreads();
    float tot = 0.f;
    #pragma unroll
    for (int a = 0; a < 8; a++) tot += sm2[a];
    const float inv = 1.0f / tot;
    for (int t = tid; t < Lr; t += 256) p[t] = tf32r(p[t] * inv);
}

extern "C" void kernel_launch(void* const* d_in, const int* in_sizes, int n_in,
                              void* d_out, int out_size)
{
    const float* x  = (const float*)d_in[0];
    // d_in[1] = cache_kv (unused: start_pos=0, L=SEQ)
    const float* fr = (const float*)d_in[2];
    const float* wq = (const float*)d_in[3];
    const float* wk = (const float*)d_in[4];
    const float* wv = (const float*)d_in[5];
    const float* wo = (const float*)d_in[6];
    float* out = (float*)d_out;

    float *xr, *wqr, *wkr, *wvr, *wor, *q, *k, *v, *attn, *sc;
    cudaGetSymbolAddress((void**)&xr,  g_xr);
    cudaGetSymbolAddress((void**)&wqr, g_wqr);
    cudaGetSymbolAddress((void**)&wkr, g_wkr);
    cudaGetSymbolAddress((void**)&wvr, g_wvr);
    cudaGetSymbolAddress((void**)&wor, g_wor);
    cudaGetSymbolAddress((void**)&q,   g_q);
    cudaGetSymbolAddress((void**)&k,   g_k);
    cudaGetSymbolAddress((void**)&v,   g_v);
    cudaGetSymbolAddress((void**)&attn,g_attn);
    cudaGetSymbolAddress((void**)&sc,  g_scores);

    cudaFuncSetAttribute(gemm_cp<0>, cudaFuncAttributeMaxDynamicSharedMemorySize, SMEM0);
    cudaFuncSetAttribute(gemm_cp<1>, cudaFuncAttributeMaxDynamicSharedMemorySize, SMEM1);

    const float rs = 0.08838834764831845f;   // 1/sqrt(128)

    // Pre-round all GEMM operands to tf32 (RNA) once.
    {
        long n;
        n = (long)SEQ * DIM / 4;   round_copy<<<(n + 255) / 256, 256>>>((const float4*)x,  (float4*)xr,  n);
        n = (long)DIM * DIM / 4;   round_copy<<<(n + 255) / 256, 256>>>((const float4*)wq, (float4*)wqr, n);
        n = (long)DIM * KVDIM / 4; round_copy<<<(n + 255) / 256, 256>>>((const float4*)wk, (float4*)wkr, n);
        n = (long)DIM * KVDIM / 4; round_copy<<<(n + 255) / 256, 256>>>((const float4*)wv, (float4*)wvr, n);
        n = (long)DIM * DIM / 4;   round_copy<<<(n + 255) / 256, 256>>>((const float4*)wo, (float4*)wor, n);
    }

    // Projections (B in [K,N] form, BT=0), epilogue rounded
    gemm_cp<0><<<dim3(DIM / BNT,   SEQ / BMT, 1), 256, SMEM0>>>(
        xr, wqr, q, DIM, DIM, DIM,   DIM,   0, 0, 0, 1, 1.f, 0, 0, 1);
    gemm_cp<0><<<dim3(KVDIM / BNT, SEQ / BMT, 1), 256, SMEM0>>>(
        xr, wkr, k, DIM, DIM, KVDIM, KVDIM, 0, 0, 0, 1, 1.f, 0, 0, 1);
    gemm_cp<0><<<dim3(KVDIM / BNT, SEQ / BMT, 1), 256, SMEM0>>>(
        xr, wvr, v, DIM, DIM, KVDIM, KVDIM, 0, 0, 0, 1, 1.f, 0, 0, 1);

    rope_kernel<<<SEQ * (NHEADS + NKV) * (HD / 2) / 256, 256>>>(q, k, fr);

    // scores[h] = (Q_h @ K_{h/4}^T) * rs, causal  (B = k in [N,K] form, BT=1)
    gemm_cp<1><<<dim3(SEQ / BNT, SEQ / BMT, NHEADS), 256, SMEM1>>>(
        q, k, sc, HD, DIM, KVDIM, SEQ,
        (long)HD, (long)HD, (long)SEQ * SEQ, 4, rs, 1, 0, 0);

    softmax_rows<<<NHEADS * SEQ, 256>>>(sc);

    // attn[h] = P_h @ V_{h/4}  (B = v in [K,N] form, BT=0; K truncated causally)
    gemm_cp<0><<<dim3(HD / BNT, SEQ / BMT, NHEADS), 256, SMEM0>>>(
        sc, v, attn, SEQ, SEQ, KVDIM, DIM,
        (long)SEQ * SEQ, (long)HD, (long)HD, 4, 1.f, 0, 1, 1);

    // out = attn @ wo
    gemm_cp<0><<<dim3(DIM / BNT, SEQ / BMT, 1), 256, SMEM0>>>(
        attn, wor, out, DIM, DIM, DIM, DIM, 0, 0, 0, 1, 1.f, 0, 0, 0);
}

// round 10
// speedup vs baseline: 1.9369x; 1.9109x over previous
#include <cuda_runtime.h>
#include <cuda_fp16.h>
#include <cstdint>

#define SEQ    2048
#define DIM    4096
#define NHEADS 32
#define NKV    8
#define HD     128
#define KVDIM  1024

#define BMT 128
#define BNT 128
#define BKT 32
#define NSTAGE 4
#define STRH   40                    // smem row stride in halves (80B)
#define STAGEB (128 * STRH * 2)      // 10240 B per operand stage
#define GSMEM  (2 * NSTAGE * STAGEB) // 81920 B

// ---- scratch (device globals: sanctioned no-alloc workaround) ----
__device__ __half g_xh  [(size_t)SEQ * DIM];
__device__ __half g_wqT [(size_t)DIM * DIM];
__device__ __half g_wkT [(size_t)KVDIM * DIM];
__device__ __half g_wvT [(size_t)KVDIM * DIM];
__device__ __half g_woT [(size_t)DIM * DIM];
__device__ __half g_qh  [(size_t)SEQ * DIM];
__device__ __half g_kh  [(size_t)SEQ * KVDIM];
__device__ __half g_vh  [(size_t)SEQ * KVDIM];
__device__ __half g_vth [(size_t)KVDIM * SEQ];
__device__ __half g_attnh[(size_t)SEQ * DIM];
__device__ __half g_p   [(size_t)NHEADS * SEQ * SEQ];   // 256 MB
__device__ float  g_sc  [(size_t)NHEADS * SEQ * SEQ];   // 512 MB

static __device__ __forceinline__ uint32_t smem_u32(const void* p) {
    uint32_t a;
    asm("{ .reg .u64 t; cvta.to.shared.u64 t, %1; cvt.u32.u64 %0, t; }" : "=r"(a) : "l"(p));
    return a;
}
static __device__ __forceinline__ void cp16(uint32_t s, const void* g) {
    asm volatile("cp.async.cg.shared.global [%0], [%1], 16;" :: "r"(s), "l"(g));
}
static __device__ __forceinline__ void cp_commit() {
    asm volatile("cp.async.commit_group;" ::: "memory");
}
template<int N> static __device__ __forceinline__ void cp_wait() {
    asm volatile("cp.async.wait_group %0;" :: "n"(N) : "memory");
}

// C[M,N] = (A[M,K] @ B[N,K]^T) * scale via fp16 mma.sync m16n8k16 (fp32 accum).
// A, B are __half, K-major. 4-stage cp.async pipeline, BK=32.
// MODE 0: fp32 store, causal mask + scale supported (scores / final out)
// MODE 1: half store (v proj, PV)
// MODE 2: half store with fused RoPE using f (q/k projections)
// causal: fully-masked tiles write NOTHING. klim: truncate K at m0+BMT.
template<int MODE>
__global__ void __launch_bounds__(256, 2)
gemm_h(const __half* __restrict__ A, const __half* __restrict__ B,
       float* __restrict__ Cf, __half* __restrict__ Ch, const float* __restrict__ f,
       int K, int lda, int ldb, int ldc,
       long sA, long sB, long sC, int bdiv,
       float scale, int causal, int klim)
{
    extern __shared__ char smem[];
    const int tid  = threadIdx.x;
    const int lane = tid & 31, warp = tid >> 5;
    const int m0 = blockIdx.y * BMT, n0 = blockIdx.x * BNT;
    if (causal && n0 >= m0 + BMT) return;

    const int z = blockIdx.z;
    A += (long)z * sA;
    B += (long)(z / bdiv) * sB;

    int Keff = K;
    if (klim) { int lim = m0 + BMT; if (lim < Keff) Keff = lim; }
    const int nkt = Keff / BKT;

    const uint32_t sbA = smem_u32(smem);
    const uint32_t sbB = sbA + NSTAGE * STAGEB;

    // producer: row = tid>>1 (128 rows), half-row hf = tid&1 (16 halves = 32B)
    const int prow = tid >> 1, phf = tid & 1;
    const __half*  Agp = A + (long)(m0 + prow) * lda + phf * 16;
    const __half*  Bgp = B + (long)(n0 + prow) * ldb + phf * 16;
    const uint32_t AsO = sbA + (uint32_t)(prow * (STRH * 2) + phf * 32);
    const uint32_t BsO = sbB + (uint32_t)(prow * (STRH * 2) + phf * 32);

    auto issue = [&](int kt, int st) {
        const __half* ga = Agp + kt * BKT;
        const __half* gb = Bgp + kt * BKT;
        const uint32_t sa = AsO + st * STAGEB;
        const uint32_t sb = BsO + st * STAGEB;
        cp16(sa,      ga);
        cp16(sa + 16, ga + 8);
        cp16(sb,      gb);
        cp16(sb + 16, gb + 8);
    };

    const int wm = warp >> 2, wn = warp & 3;   // 2x4 warps -> 64x32 warp tile
    const int g  = lane >> 2, tg = lane & 3;

    float acc[4][4][4];
    #pragma unroll
    for (int a = 0; a < 4; a++)
        #pragma unroll
        for (int b = 0; b < 4; b++)
            #pragma unroll
            for (int c = 0; c < 4; c++) acc[a][b][c] = 0.f;

    #pragma unroll
    for (int p = 0; p < NSTAGE - 1; p++) {
        if (p < nkt) issue(p, p);
        cp_commit();
    }

    int st = 0, pst = NSTAGE - 1;
    for (int kt = 0; kt < nkt; kt++) {
        cp_wait<NSTAGE - 2>();
        __syncthreads();
        if (kt + NSTAGE - 1 < nkt) issue(kt + NSTAGE - 1, pst);
        cp_commit();

        const uint32_t* as32 = (const uint32_t*)(smem + st * STAGEB);
        const uint32_t* bs32 = (const uint32_t*)(smem + NSTAGE * STAGEB + st * STAGEB);
        #pragma unroll
        for (int kk2 = 0; kk2 < 16; kk2 += 8) {      // k offset in 32-bit words
            uint32_t af[4][4], bf[4][2];
            #pragma unroll
            for (int im = 0; im < 4; im++) {
                const int m = wm * 64 + im * 16;
                const int b0 = (m + g) * 20 + kk2 + tg;
                af[im][0] = as32[b0];
                af[im][1] = as32[b0 + 160];
                af[im][2] = as32[b0 + 4];
                af[im][3] = as32[b0 + 164];
            }
            #pragma unroll
            for (int in = 0; in < 4; in++) {
                const int n = wn * 32 + in * 8;
                const int b0 = (n + g) * 20 + kk2 + tg;
                bf[in][0] = bs32[b0];
                bf[in][1] = bs32[b0 + 4];
            }
            #pragma unroll
            for (int im = 0; im < 4; im++)
                #pragma unroll
                for (int in = 0; in < 4; in++)
                    asm volatile(
                        "mma.sync.aligned.m16n8k16.row.col.f32.f16.f16.f32 "
                        "{%0,%1,%2,%3}, {%4,%5,%6,%7}, {%8,%9}, {%0,%1,%2,%3};"
                        : "+f"(acc[im][in][0]), "+f"(acc[im][in][1]),
                          "+f"(acc[im][in][2]), "+f"(acc[im][in][3])
                        : "r"(af[im][0]), "r"(af[im][1]), "r"(af[im][2]), "r"(af[im][3]),
                          "r"(bf[in][0]), "r"(bf[in][1]));
        }
        st  = (st  == NSTAGE - 1) ? 0 : st + 1;
        pst = (pst == NSTAGE - 1) ? 0 : pst + 1;
    }

    // ---- epilogue ----
    #pragma unroll
    for (int im = 0; im < 4; im++) {
        const int r0 = m0 + wm * 64 + im * 16 + g;
        #pragma unroll
        for (int in = 0; in < 4; in++) {
            const int c = n0 + wn * 32 + in * 8 + 2 * tg;
            float v0 = acc[im][in][0], v1 = acc[im][in][1];
            float v2 = acc[im][in][2], v3 = acc[im][in][3];
            if (MODE == 0) {
                v0 *= scale; v1 *= scale; v2 *= scale; v3 *= scale;
                if (causal) {
                    if (c     > r0    ) v0 = -1e30f;
                    if (c + 1 > r0    ) v1 = -1e30f;
                    if (c     > r0 + 8) v2 = -1e30f;
                    if (c + 1 > r0 + 8) v3 = -1e30f;
                }
                float* Cp = Cf + (long)z * sC;
                *(float2*)&Cp[(long)r0 * ldc + c]       = make_float2(v0, v1);
                *(float2*)&Cp[(long)(r0 + 8) * ldc + c] = make_float2(v2, v3);
            } else {
                if (MODE == 2) {   // fused RoPE: (v0,v1) is a rotation pair
                    const float2 fa = *(const float2*)&f[(long)r0 * HD + (c & (HD - 1))];
                    const float2 fb = *(const float2*)&f[(long)(r0 + 8) * HD + (c & (HD - 1))];
                    float t0 = v0 * fa.x - v1 * fa.y;
                    float t1 = v0 * fa.y + v1 * fa.x;
                    float t2 = v2 * fb.x - v3 * fb.y;
                    float t3 = v2 * fb.y + v3 * fb.x;
                    v0 = t0; v1 = t1; v2 = t2; v3 = t3;
                }
                __half* Cp = Ch + (long)z * sC;
                *(__half2*)&Cp[(long)r0 * ldc + c] =
                    __floats2half2_rn(v0, v1);
                *(__half2*)&Cp[(long)(r0 + 8) * ldc + c] =
                    __floats2half2_rn(v2, v3);
            }
        }
    }
}

// float -> half elementwise (4/thread)
__global__ void conv_h(const float4* __restrict__ in, __half2* __restrict__ out, long n4)
{
    long i = (long)blockIdx.x * blockDim.x + threadIdx.x;
    if (i >= n4) return;
    float4 v = in[i];
    out[2 * i]     = __floats2half2_rn(v.x, v.y);
    out[2 * i + 1] = __floats2half2_rn(v.z, v.w);
}

// float [R,C] -> half [C,R] transpose (32x32 tiles, block 32x8)
__global__ void transpose_fh(const float* __restrict__ in, __half* __restrict__ out,
                             int R, int C)
{
    __shared__ float t[32][33];
    const int bx = blockIdx.x * 32, by = blockIdx.y * 32;
    const int x = bx + threadIdx.x;
    #pragma unroll
    for (int j = 0; j < 32; j += 8)
        t[threadIdx.y + j][threadIdx.x] = in[(long)(by + threadIdx.y + j) * C + x];
    __syncthreads();
    const int x2 = by + threadIdx.x;
    #pragma unroll
    for (int j = 0; j < 32; j += 8)
        out[(long)(bx + threadIdx.y + j) * R + x2] =
            __float2half_rn(t[threadIdx.x][threadIdx.y + j]);
}

// half [R,C] -> half [C,R] transpose
__global__ void transpose_hh(const __half* __restrict__ in, __half* __restrict__ out,
                             int R, int C)
{
    __shared__ __half t[32][33];
    const int bx = blockIdx.x * 32, by = blockIdx.y * 32;
    const int x = bx + threadIdx.x;
    #pragma unroll
    for (int j = 0; j < 32; j += 8)
        t[threadIdx.y + j][threadIdx.x] = in[(long)(by + threadIdx.y + j) * C + x];
    __syncthreads();
    const int x2 = by + threadIdx.x;
    #pragma unroll
    for (int j = 0; j < 32; j += 8)
        out[(long)(bx + threadIdx.y + j) * R + x2] = t[threadIdx.x][threadIdx.y + j];
}

// Row softmax on fp32 scores, truncated at 128-aligned causal boundary;
// writes half P (only [0,Lr) — PV never reads beyond).
__global__ void softmax_rows(const float* __restrict__ sc, __half* __restrict__ p)
{
    const long row = blockIdx.x;             // h*SEQ + i
    const int  i   = (int)(row % SEQ);
    const int  Lr  = ((i >> 7) + 1) << 7;
    const float* s = sc + row * (long)SEQ;
    __half* ph = p + row * (long)SEQ;
    const int tid = threadIdx.x;
    __shared__ float sm1[8], sm2[8];

    float mx = -3.0e38f;
    for (int t = tid; t < Lr; t += 256) mx = fmaxf(mx, s[t]);
    #pragma unroll
    for (int o = 16; o > 0; o >>= 1) mx = fmaxf(mx, __shfl_xor_sync(0xffffffffu, mx, o));
    if ((tid & 31) == 0) sm1[tid >> 5] = mx;
    __syncthreads();
    mx = sm1[0];
    #pragma unroll
    for (int a = 1; a < 8; a++) mx = fmaxf(mx, sm1[a]);

    float sum = 0.f;
    for (int t = tid; t < Lr; t += 256) sum += __expf(s[t] - mx);
    #pragma unroll
    for (int o = 16; o > 0; o >>= 1) sum += __shfl_xor_sync(0xffffffffu, sum, o);
    if ((tid & 31) == 0) sm2[tid >> 5] = sum;
    __syncthreads();
    float tot = 0.f;
    #pragma unroll
    for (int a = 0; a < 8; a++) tot += sm2[a];
    const float inv = 1.0f / tot;
    for (int t = tid; t < Lr; t += 256)
        ph[t] = __float2half_rn(__expf(s[t] - mx) * inv);
}

extern "C" void kernel_launch(void* const* d_in, const int* in_sizes, int n_in,
                              void* d_out, int out_size)
{
    const float* x  = (const float*)d_in[0];
    // d_in[1] = cache_kv (unused: start_pos=0, L=SEQ)
    const float* fr = (const float*)d_in[2];
    const float* wq = (const float*)d_in[3];
    const float* wk = (const float*)d_in[4];
    const float* wv = (const float*)d_in[5];
    const float* wo = (const float*)d_in[6];
    float* out = (float*)d_out;

    __half *xh, *wqT, *wkT, *wvT, *woT, *qh, *kh, *vh, *vth, *attnh, *p;
    float *sc;
    cudaGetSymbolAddress((void**)&xh,   g_xh);
    cudaGetSymbolAddress((void**)&wqT,  g_wqT);
    cudaGetSymbolAddress((void**)&wkT,  g_wkT);
    cudaGetSymbolAddress((void**)&wvT,  g_wvT);
    cudaGetSymbolAddress((void**)&woT,  g_woT);
    cudaGetSymbolAddress((void**)&qh,   g_qh);
    cudaGetSymbolAddress((void**)&kh,   g_kh);
    cudaGetSymbolAddress((void**)&vh,   g_vh);
    cudaGetSymbolAddress((void**)&vth,  g_vth);
    cudaGetSymbolAddress((void**)&attnh,g_attnh);
    cudaGetSymbolAddress((void**)&p,    g_p);
    cudaGetSymbolAddress((void**)&sc,   g_sc);

    cudaFuncSetAttribute(gemm_h<0>, cudaFuncAttributeMaxDynamicSharedMemorySize, GSMEM);
    cudaFuncSetAttribute(gemm_h<1>, cudaFuncAttributeMaxDynamicSharedMemorySize, GSMEM);
    cudaFuncSetAttribute(gemm_h<2>, cudaFuncAttributeMaxDynamicSharedMemorySize, GSMEM);

    const float rs = 0.08838834764831845f;   // 1/sqrt(128)
    dim3 tb(32, 8);

    // Convert x to half; transpose+convert weights to [N,K] half.
    {
        long n4 = (long)SEQ * DIM / 4;
        conv_h<<<(n4 + 255) / 256, 256>>>((const float4*)x, (__half2*)xh, n4);
    }
    transpose_fh<<<dim3(DIM / 32,   DIM / 32), tb>>>(wq, wqT, DIM, DIM);
    transpose_fh<<<dim3(KVDIM / 32, DIM / 32), tb>>>(wk, wkT, DIM, KVDIM);
    transpose_fh<<<dim3(KVDIM / 32, DIM / 32), tb>>>(wv, wvT, DIM, KVDIM);
    transpose_fh<<<dim3(DIM / 32,   DIM / 32), tb>>>(wo, woT, DIM, DIM);

    // Projections. Q/K fuse RoPE (MODE 2); V plain half (MODE 1).
    gemm_h<2><<<dim3(DIM / BNT,   SEQ / BMT, 1), 256, GSMEM>>>(
        xh, wqT, nullptr, qh, fr, DIM, DIM, DIM, DIM, 0, 0, 0, 1, 1.f, 0, 0);
    gemm_h<2><<<dim3(KVDIM / BNT, SEQ / BMT, 1), 256, GSMEM>>>(
        xh, wkT, nullptr, kh, fr, DIM, DIM, DIM, KVDIM, 0, 0, 0, 1, 1.f, 0, 0);
    gemm_h<1><<<dim3(KVDIM / BNT, SEQ / BMT, 1), 256, GSMEM>>>(
        xh, wvT, nullptr, vh, nullptr, DIM, DIM, DIM, KVDIM, 0, 0, 0, 1, 1.f, 0, 0);

    // V^T per kv-head: vth[1024, 2048]
    transpose_hh<<<dim3(KVDIM / 32, SEQ / 32), tb>>>(vh, vth, SEQ, KVDIM);

    // scores[h] = (Q_h @ K_{h/4}^T) * rs, causal, fp32 out
    gemm_h<0><<<dim3(SEQ / BNT, SEQ / BMT, NHEADS), 256, GSMEM>>>(
        qh, kh, sc, nullptr, nullptr, HD, DIM, KVDIM, SEQ,
        (long)HD, (long)HD, (long)SEQ * SEQ, 4, rs, 1, 0);

    softmax_rows<<<NHEADS * SEQ, 256>>>(sc, p);

    // attn[h] = P_h @ V_{h/4}^T^T  (B = vth rows, K-major), K truncated causally
    gemm_h<1><<<dim3(HD / BNT, SEQ / BMT, NHEADS), 256, GSMEM>>>(
        p, vth, nullptr, attnh, nullptr, SEQ, SEQ, SEQ, DIM,
        (long)SEQ * SEQ, (long)HD * SEQ, (long)HD, 4, 1.f, 0, 1);

    // out = attn @ wo, fp32 out
    gemm_h<0><<<dim3(DIM / BNT, SEQ / BMT, 1), 256, GSMEM>>>(
        attnh, woT, out, nullptr, nullptr, DIM, DIM, DIM, DIM,
        0, 0, 0, 1, 1.f, 0, 0);
}

// round 13
// speedup vs baseline: 2.2354x; 1.1541x over previous
#include <cuda_runtime.h>
#include <cuda_fp16.h>
#include <cstdint>

#define SEQ    2048
#define DIM    4096
#define NHEADS 32
#define NKV    8
#define HD     128
#define KVDIM  1024

#define BMT 128
#define BNT 128
#define BKT 32
#define NSTAGE 4
#define STAGEB 8192                   // 128 rows x 64B (32 halves), swizzled
#define GSMEM  (2 * NSTAGE * STAGEB)  // 65536 B

// ---- scratch (device globals: sanctioned no-alloc workaround) ----
__device__ __half g_xh  [(size_t)SEQ * DIM];
__device__ __half g_wqT [(size_t)DIM * DIM];
__device__ __half g_wkT [(size_t)KVDIM * DIM];
__device__ __half g_wvT [(size_t)KVDIM * DIM];
__device__ __half g_woT [(size_t)DIM * DIM];
__device__ __half g_qh  [(size_t)SEQ * DIM];
__device__ __half g_kh  [(size_t)SEQ * KVDIM];
__device__ __half g_vh  [(size_t)SEQ * KVDIM];
__device__ __half g_vth [(size_t)KVDIM * SEQ];
__device__ __half g_attnh[(size_t)SEQ * DIM];
__device__ __half g_p   [(size_t)NHEADS * SEQ * SEQ];
__device__ float  g_sc  [(size_t)NHEADS * SEQ * SEQ];

static __device__ __forceinline__ uint32_t smem_u32(const void* p) {
    uint32_t a;
    asm("{ .reg .u64 t; cvta.to.shared.u64 t, %1; cvt.u32.u64 %0, t; }" : "=r"(a) : "l"(p));
    return a;
}
static __device__ __forceinline__ void cp16(uint32_t s, const void* g) {
    asm volatile("cp.async.cg.shared.global [%0], [%1], 16;" :: "r"(s), "l"(g));
}
static __device__ __forceinline__ void cp_commit() {
    asm volatile("cp.async.commit_group;" ::: "memory");
}
template<int N> static __device__ __forceinline__ void cp_wait() {
    asm volatile("cp.async.wait_group %0;" :: "n"(N) : "memory");
}
static __device__ __forceinline__ void ldm4(uint32_t* r, uint32_t a) {
    asm volatile("ldmatrix.sync.aligned.m8n8.x4.shared.b16 {%0,%1,%2,%3}, [%4];"
                 : "=r"(r[0]), "=r"(r[1]), "=r"(r[2]), "=r"(r[3]) : "r"(a));
}

// C[M,N] = (A[M,K] @ B[N,K]^T) * scale via fp16 mma.sync m16n8k16 (fp32 accum).
// A, B __half K-major. 4-stage cp.async pipeline, BK=32, ldmatrix fragments.
// Smem tile: 128 rows x 4 chunks(16B); physical chunk = c ^ ((row>>1)&3)
// (Swizzle<2,3,3>): conflict-free for both cp.async stores and ldmatrix reads.
// MODE 0: fp32 store + scale + causal; MODE 1: half store; MODE 2: half + fused RoPE.
template<int MODE>
__global__ void __launch_bounds__(256, 2)
gemm_h(const __half* __restrict__ A, const __half* __restrict__ B,
       float* __restrict__ Cf, __half* __restrict__ Ch, const float* __restrict__ f,
       int K, int lda, int ldb, int ldc,
       long sA, long sB, long sC, int bdiv,
       float scale, int causal, int klim)
{
    extern __shared__ char smem[];
    const int tid  = threadIdx.x;
    const int lane = tid & 31, warp = tid >> 5;
    const int m0 = blockIdx.y * BMT, n0 = blockIdx.x * BNT;
    if (causal && n0 >= m0 + BMT) return;

    const int z = blockIdx.z;
    A += (long)z * sA;
    B += (long)(z / bdiv) * sB;

    int Keff = K;
    if (klim) { int lim = m0 + BMT; if (lim < Keff) Keff = lim; }
    const int nkt = Keff / BKT;

    const uint32_t sbA = smem_u32(smem);
    const uint32_t sbB = sbA + NSTAGE * STAGEB;

    // ---- producer: thread -> (row tid>>1, chunk pair (tid&1)*2) ----
    const int prow = tid >> 1, pc = (tid & 1) * 2;
    const int px   = (prow >> 1) & 3;
    const __half*  Agp = A + (long)(m0 + prow) * lda + pc * 8;
    const __half*  Bgp = B + (long)(n0 + prow) * ldb + pc * 8;
    const uint32_t AsO = sbA + (uint32_t)(prow * 64);
    const uint32_t BsO = sbB + (uint32_t)(prow * 64);
    const uint32_t c0 = (uint32_t)((pc ^ px) << 4), c1 = (uint32_t)(((pc + 1) ^ px) << 4);

    auto issue = [&](int kt, int st) {
        const __half* ga = Agp + kt * BKT;
        const __half* gb = Bgp + kt * BKT;
        const uint32_t sa = AsO + st * STAGEB;
        const uint32_t sb = BsO + st * STAGEB;
        cp16(sa + c0, ga);
        cp16(sa + c1, ga + 8);
        cp16(sb + c0, gb);
        cp16(sb + c1, gb + 8);
    };

    // ---- consumer: ldmatrix address precompute ----
    const int wm = warp >> 2, wn = warp & 3;   // 2x4 warps -> 64x32 warp tile
    const int lrow = lane & 15, lsel = lane >> 4;

    uint32_t aBase[4], aCh[4][2];
    #pragma unroll
    for (int im = 0; im < 4; im++) {
        const int r = wm * 64 + im * 16 + lrow;
        aBase[im] = sbA + (uint32_t)(r * 64);
        const int x = (r >> 1) & 3;
        aCh[im][0] = (uint32_t)(((0 * 2 + lsel) ^ x) << 4);
        aCh[im][1] = (uint32_t)(((1 * 2 + lsel) ^ x) << 4);
    }
    uint32_t bBase[2], bCh[2][2];
    #pragma unroll
    for (int ip = 0; ip < 2; ip++) {
        const int r = wn * 32 + ip * 16 + lrow;
        bBase[ip] = sbB + (uint32_t)(r * 64);
        const int x = (r >> 1) & 3;
        bCh[ip][0] = (uint32_t)(((0 * 2 + lsel) ^ x) << 4);
        bCh[ip][1] = (uint32_t)(((1 * 2 + lsel) ^ x) << 4);
    }

    float acc[4][4][4];
    #pragma unroll
    for (int a = 0; a < 4; a++)
        #pragma unroll
        for (int b = 0; b < 4; b++)
            #pragma unroll
            for (int c = 0; c < 4; c++) acc[a][b][c] = 0.f;

    #pragma unroll
    for (int p = 0; p < NSTAGE - 1; p++) {
        if (p < nkt) issue(p, p);
        cp_commit();
    }

    int st = 0, pst = NSTAGE - 1;
    for (int kt = 0; kt < nkt; kt++) {
        cp_wait<NSTAGE - 2>();
        __syncthreads();
        if (kt + NSTAGE - 1 < nkt) issue(kt + NSTAGE - 1, pst);
        cp_commit();

        const uint32_t stO = (uint32_t)(st * STAGEB);
        #pragma unroll
        for (int kk = 0; kk < 2; kk++) {
            uint32_t af[4][4], bf[2][4];
            #pragma unroll
            for (int im = 0; im < 4; im++) ldm4(af[im], aBase[im] + stO + aCh[im][kk]);
            #pragma unroll
            for (int ip = 0; ip < 2; ip++) ldm4(bf[ip], bBase[ip] + stO + bCh[ip][kk]);
            #pragma unroll
            for (int im = 0; im < 4; im++)
                #pragma unroll
                for (int ip = 0; ip < 2; ip++) {
                    asm volatile(
                        "mma.sync.aligned.m16n8k16.row.col.f32.f16.f16.f32 "
                        "{%0,%1,%2,%3}, {%4,%5,%6,%7}, {%8,%9}, {%0,%1,%2,%3};"
                        : "+f"(acc[im][2*ip][0]), "+f"(acc[im][2*ip][1]),
                          "+f"(acc[im][2*ip][2]), "+f"(acc[im][2*ip][3])
                        : "r"(af[im][0]), "r"(af[im][1]), "r"(af[im][2]), "r"(af[im][3]),
                          "r"(bf[ip][0]), "r"(bf[ip][2]));
                    asm volatile(
                        "mma.sync.aligned.m16n8k16.row.col.f32.f16.f16.f32 "
                        "{%0,%1,%2,%3}, {%4,%5,%6,%7}, {%8,%9}, {%0,%1,%2,%3};"
                        : "+f"(acc[im][2*ip+1][0]), "+f"(acc[im][2*ip+1][1]),
                          "+f"(acc[im][2*ip+1][2]), "+f"(acc[im][2*ip+1][3])
                        : "r"(af[im][0]), "r"(af[im][1]), "r"(af[im][2]), "r"(af[im][3]),
                          "r"(bf[ip][1]), "r"(bf[ip][3]));
                }
        }
        st  = (st  == NSTAGE - 1) ? 0 : st + 1;
        pst = (pst == NSTAGE - 1) ? 0 : pst + 1;
    }

    // ---- epilogue (identical math to R10) ----
    const int g = lane >> 2, tg = lane & 3;
    #pragma unroll
    for (int im = 0; im < 4; im++) {
        const int r0 = m0 + wm * 64 + im * 16 + g;
        #pragma unroll
        for (int in = 0; in < 4; in++) {
            const int c = n0 + wn * 32 + in * 8 + 2 * tg;
            float v0 = acc[im][in][0], v1 = acc[im][in][1];
            float v2 = acc[im][in][2], v3 = acc[im][in][3];
            if (MODE == 0) {
                v0 *= scale; v1 *= scale; v2 *= scale; v3 *= scale;
                if (causal) {
                    if (c     > r0    ) v0 = -1e30f;
                    if (c + 1 > r0    ) v1 = -1e30f;
                    if (c     > r0 + 8) v2 = -1e30f;
                    if (c + 1 > r0 + 8) v3 = -1e30f;
                }
                float* Cp = Cf + (long)z * sC;
                *(float2*)&Cp[(long)r0 * ldc + c]       = make_float2(v0, v1);
                *(float2*)&Cp[(long)(r0 + 8) * ldc + c] = make_float2(v2, v3);
            } else {
                if (MODE == 2) {
                    const float2 fa = *(const float2*)&f[(long)r0 * HD + (c & (HD - 1))];
                    const float2 fb = *(const float2*)&f[(long)(r0 + 8) * HD + (c & (HD - 1))];
                    float t0 = v0 * fa.x - v1 * fa.y;
                    float t1 = v0 * fa.y + v1 * fa.x;
                    float t2 = v2 * fb.x - v3 * fb.y;
                    float t3 = v2 * fb.y + v3 * fb.x;
                    v0 = t0; v1 = t1; v2 = t2; v3 = t3;
                }
                __half* Cp = Ch + (long)z * sC;
                *(__half2*)&Cp[(long)r0 * ldc + c]       = __floats2half2_rn(v0, v1);
                *(__half2*)&Cp[(long)(r0 + 8) * ldc + c] = __floats2half2_rn(v2, v3);
            }
        }
    }
}

// float -> half elementwise (4/thread)
__global__ void conv_h(const float4* __restrict__ in, __half2* __restrict__ out, long n4)
{
    long i = (long)blockIdx.x * blockDim.x + threadIdx.x;
    if (i >= n4) return;
    float4 v = in[i];
    out[2 * i]     = __floats2half2_rn(v.x, v.y);
    out[2 * i + 1] = __floats2half2_rn(v.z, v.w);
}

// float [R,C] -> half [C,R] transpose
__global__ void transpose_fh(const float* __restrict__ in, __half* __restrict__ out,
                             int R, int C)
{
    __shared__ float t[32][33];
    const int bx = blockIdx.x * 32, by = blockIdx.y * 32;
    const int x = bx + threadIdx.x;
    #pragma unroll
    for (int j = 0; j < 32; j += 8)
        t[threadIdx.y + j][threadIdx.x] = in[(long)(by + threadIdx.y + j) * C + x];
    __syncthreads();
    const int x2 = by + threadIdx.x;
    #pragma unroll
    for (int j = 0; j < 32; j += 8)
        out[(long)(bx + threadIdx.y + j) * R + x2] =
            __float2half_rn(t[threadIdx.x][threadIdx.y + j]);
}

// half [R,C] -> half [C,R] transpose
__global__ void transpose_hh(const __half* __restrict__ in, __half* __restrict__ out,
                             int R, int C)
{
    __shared__ __half t[32][33];
    const int bx = blockIdx.x * 32, by = blockIdx.y * 32;
    const int x = bx + threadIdx.x;
    #pragma unroll
    for (int j = 0; j < 32; j += 8)
        t[threadIdx.y + j][threadIdx.x] = in[(long)(by + threadIdx.y + j) * C + x];
    __syncthreads();
    const int x2 = by + threadIdx.x;
    #pragma unroll
    for (int j = 0; j < 32; j += 8)
        out[(long)(bx + threadIdx.y + j) * R + x2] = t[threadIdx.x][threadIdx.y + j];
}

// Single-pass row softmax: scores staged in smem, read from gmem once.
__global__ void softmax_rows(const float* __restrict__ sc, __half* __restrict__ p)
{
    __shared__ float buf[2048];
    __shared__ float red[8];
    const long row = blockIdx.x;             // h*SEQ + i
    const int  i   = (int)(row % SEQ);
    const int  Lr  = ((i >> 7) + 1) << 7;
    const float* s = sc + row * (long)SEQ;
    __half* ph = p + row * (long)SEQ;
    const int tid = threadIdx.x;

    float mx = -3.0e38f;
    for (int t = tid; t < Lr; t += 256) {
        float v = s[t];
        buf[t] = v;
        mx = fmaxf(mx, v);
    }
    #pragma unroll
    for (int o = 16; o > 0; o >>= 1) mx = fmaxf(mx, __shfl_xor_sync(0xffffffffu, mx, o));
    if ((tid & 31) == 0) red[tid >> 5] = mx;
    __syncthreads();
    mx = red[0];
    #pragma unroll
    for (int a = 1; a < 8; a++) mx = fmaxf(mx, red[a]);
    __syncthreads();

    float sum = 0.f;
    for (int t = tid; t < Lr; t += 256) {
        float e = __expf(buf[t] - mx);
        buf[t] = e;
        sum += e;
    }
    #pragma unroll
    for (int o = 16; o > 0; o >>= 1) sum += __shfl_xor_sync(0xffffffffu, sum, o);
    if ((tid & 31) == 0) red[tid >> 5] = sum;
    __syncthreads();
    float tot = 0.f;
    #pragma unroll
    for (int a = 0; a < 8; a++) tot += red[a];
    const float inv = 1.0f / tot;
    for (int t = tid; t < Lr; t += 256)
        ph[t] = __float2half_rn(buf[t] * inv);
}

extern "C" void kernel_launch(void* const* d_in, const int* in_sizes, int n_in,
                              void* d_out, int out_size)
{
    const float* x  = (const float*)d_in[0];
    // d_in[1] = cache_kv (unused: start_pos=0, L=SEQ)
    const float* fr = (const float*)d_in[2];
    const float* wq = (const float*)d_in[3];
    const float* wk = (const float*)d_in[4];
    const float* wv = (const float*)d_in[5];
    const float* wo = (const float*)d_in[6];
    float* out = (float*)d_out;

    __half *xh, *wqT, *wkT, *wvT, *woT, *qh, *kh, *vh, *vth, *attnh, *p;
    float *sc;
    cudaGetSymbolAddress((void**)&xh,   g_xh);
    cudaGetSymbolAddress((void**)&wqT,  g_wqT);
    cudaGetSymbolAddress((void**)&wkT,  g_wkT);
    cudaGetSymbolAddress((void**)&wvT,  g_wvT);
    cudaGetSymbolAddress((void**)&woT,  g_woT);
    cudaGetSymbolAddress((void**)&qh,   g_qh);
    cudaGetSymbolAddress((void**)&kh,   g_kh);
    cudaGetSymbolAddress((void**)&vh,   g_vh);
    cudaGetSymbolAddress((void**)&vth,  g_vth);
    cudaGetSymbolAddress((void**)&attnh,g_attnh);
    cudaGetSymbolAddress((void**)&p,    g_p);
    cudaGetSymbolAddress((void**)&sc,   g_sc);

    cudaFuncSetAttribute(gemm_h<0>, cudaFuncAttributeMaxDynamicSharedMemorySize, GSMEM);
    cudaFuncSetAttribute(gemm_h<1>, cudaFuncAttributeMaxDynamicSharedMemorySize, GSMEM);
    cudaFuncSetAttribute(gemm_h<2>, cudaFuncAttributeMaxDynamicSharedMemorySize, GSMEM);

    const float rs = 0.08838834764831845f;   // 1/sqrt(128)
    dim3 tb(32, 8);

    {
        long n4 = (long)SEQ * DIM / 4;
        conv_h<<<(n4 + 255) / 256, 256>>>((const float4*)x, (__half2*)xh, n4);
    }
    transpose_fh<<<dim3(DIM / 32,   DIM / 32), tb>>>(wq, wqT, DIM, DIM);
    transpose_fh<<<dim3(KVDIM / 32, DIM / 32), tb>>>(wk, wkT, DIM, KVDIM);
    transpose_fh<<<dim3(KVDIM / 32, DIM / 32), tb>>>(wv, wvT, DIM, KVDIM);
    transpose_fh<<<dim3(DIM / 32,   DIM / 32), tb>>>(wo, woT, DIM, DIM);

    // Projections. Q/K fuse RoPE (MODE 2); V plain half (MODE 1).
    gemm_h<2><<<dim3(DIM / BNT,   SEQ / BMT, 1), 256, GSMEM>>>(
        xh, wqT, nullptr, qh, fr, DIM, DIM, DIM, DIM, 0, 0, 0, 1, 1.f, 0, 0);
    gemm_h<2><<<dim3(KVDIM / BNT, SEQ / BMT, 1), 256, GSMEM>>>(
        xh, wkT, nullptr, kh, fr, DIM, DIM, DIM, KVDIM, 0, 0, 0, 1, 1.f, 0, 0);
    gemm_h<1><<<dim3(KVDIM / BNT, SEQ / BMT, 1), 256, GSMEM>>>(
        xh, wvT, nullptr, vh, nullptr, DIM, DIM, DIM, KVDIM, 0, 0, 0, 1, 1.f, 0, 0);

    // V^T per kv-head
    transpose_hh<<<dim3(KVDIM / 32, SEQ / 32), tb>>>(vh, vth, SEQ, KVDIM);

    // scores[h] = (Q_h @ K_{h/4}^T) * rs, causal, fp32 out
    gemm_h<0><<<dim3(SEQ / BNT, SEQ / BMT, NHEADS), 256, GSMEM>>>(
        qh, kh, sc, nullptr, nullptr, HD, DIM, KVDIM, SEQ,
        (long)HD, (long)HD, (long)SEQ * SEQ, 4, rs, 1, 0);

    softmax_rows<<<NHEADS * SEQ, 256>>>(sc, p);

    // attn[h] = P_h @ V_{h/4}  (B = vth rows, K-major), K truncated causally
    gemm_h<1><<<dim3(HD / BNT, SEQ / BMT, NHEADS), 256, GSMEM>>>(
        p, vth, nullptr, attnh, nullptr, SEQ, SEQ, SEQ, DIM,
        (long)SEQ * SEQ, (long)HD * SEQ, (long)HD, 4, 1.f, 0, 1);

    // out = attn @ wo, fp32 out
    gemm_h<0><<<dim3(DIM / BNT, SEQ / BMT, 1), 256, GSMEM>>>(
        attnh, woT, out, nullptr, nullptr, DIM, DIM, DIM, DIM,
        0, 0, 0, 1, 1.f, 0, 0);
}

// round 16
// speedup vs baseline: 2.5547x; 1.1429x over previous
#include <cuda_runtime.h>
#include <cuda_fp16.h>
#include <cstdint>
#include <cstring>

#define SEQ    2048
#define DIM    4096
#define NHEADS 32
#define NKV    8
#define HD     128
#define KVDIM  1024

#define BMT 128
#define BNT 128
#define BKT 32
#define NSTAGE 4
#define STAGEB 8192
#define GSMEM  (2 * NSTAGE * STAGEB)  // 65536 B
#define FSMEM  163840                 // flash: Q 32K + K 2x32K + V 2x32K

// ---- scratch (device globals: sanctioned no-alloc workaround) ----
__device__ __half g_xh  [(size_t)SEQ * DIM];
__device__ __half g_wqT [(size_t)DIM * DIM];
__device__ __half g_wkT [(size_t)KVDIM * DIM];
__device__ __half g_wvT [(size_t)KVDIM * DIM];
__device__ __half g_woT [(size_t)DIM * DIM];
__device__ __half g_qh  [(size_t)SEQ * DIM];
__device__ __half g_kh  [(size_t)SEQ * KVDIM];
__device__ __half g_vh  [(size_t)SEQ * KVDIM];
__device__ __half g_attnh[(size_t)SEQ * DIM];

static __device__ __forceinline__ uint32_t pack_h2(float lo, float hi) {
    __half2 h = __floats2half2_rn(lo, hi);
    uint32_t u;
    memcpy(&u, &h, 4);
    return u;
}
static __device__ __forceinline__ uint32_t smem_u32(const void* p) {
    uint32_t a;
    asm("{ .reg .u64 t; cvta.to.shared.u64 t, %1; cvt.u32.u64 %0, t; }" : "=r"(a) : "l"(p));
    return a;
}
static __device__ __forceinline__ void cp16(uint32_t s, const void* g) {
    asm volatile("cp.async.cg.shared.global [%0], [%1], 16;" :: "r"(s), "l"(g));
}
static __device__ __forceinline__ void cp_commit() {
    asm volatile("cp.async.commit_group;" ::: "memory");
}
template<int N> static __device__ __forceinline__ void cp_wait() {
    asm volatile("cp.async.wait_group %0;" :: "n"(N) : "memory");
}
static __device__ __forceinline__ void ldm4(uint32_t* r, uint32_t a) {
    asm volatile("ldmatrix.sync.aligned.m8n8.x4.shared.b16 {%0,%1,%2,%3}, [%4];"
                 : "=r"(r[0]), "=r"(r[1]), "=r"(r[2]), "=r"(r[3]) : "r"(a));
}
static __device__ __forceinline__ void ldm4t(uint32_t* r, uint32_t a) {
    asm volatile("ldmatrix.sync.aligned.m8n8.x4.trans.shared.b16 {%0,%1,%2,%3}, [%4];"
                 : "=r"(r[0]), "=r"(r[1]), "=r"(r[2]), "=r"(r[3]) : "r"(a));
}
static __device__ __forceinline__ void mma16816(float* d, const uint32_t* a,
                                                uint32_t b0, uint32_t b1) {
    asm volatile(
        "mma.sync.aligned.m16n8k16.row.col.f32.f16.f16.f32 "
        "{%0,%1,%2,%3}, {%4,%5,%6,%7}, {%8,%9}, {%0,%1,%2,%3};"
        : "+f"(d[0]), "+f"(d[1]), "+f"(d[2]), "+f"(d[3])
        : "r"(a[0]), "r"(a[1]), "r"(a[2]), "r"(a[3]), "r"(b0), "r"(b1));
}

// ================= projection / out-proj GEMM (as R13) =================
template<int MODE>
__global__ void __launch_bounds__(256, 2)
gemm_h(const __half* __restrict__ A, const __half* __restrict__ B,
       float* __restrict__ Cf, __half* __restrict__ Ch, const float* __restrict__ f,
       int K, int lda, int ldb, int ldc)
{
    extern __shared__ char smem[];
    const int tid  = threadIdx.x;
    const int lane = tid & 31, warp = tid >> 5;
    const int m0 = blockIdx.y * BMT, n0 = blockIdx.x * BNT;
    const int nkt = K / BKT;

    const uint32_t sbA = smem_u32(smem);
    const uint32_t sbB = sbA + NSTAGE * STAGEB;

    const int prow = tid >> 1, pc = (tid & 1) * 2;
    const int px   = (prow >> 1) & 3;
    const __half*  Agp = A + (long)(m0 + prow) * lda + pc * 8;
    const __half*  Bgp = B + (long)(n0 + prow) * ldb + pc * 8;
    const uint32_t AsO = sbA + (uint32_t)(prow * 64);
    const uint32_t BsO = sbB + (uint32_t)(prow * 64);
    const uint32_t c0 = (uint32_t)((pc ^ px) << 4), c1 = (uint32_t)(((pc + 1) ^ px) << 4);

    auto issue = [&](int kt, int st) {
        const __half* ga = Agp + kt * BKT;
        const __half* gb = Bgp + kt * BKT;
        const uint32_t sa = AsO + st * STAGEB;
        const uint32_t sb = BsO + st * STAGEB;
        cp16(sa + c0, ga); cp16(sa + c1, ga + 8);
        cp16(sb + c0, gb); cp16(sb + c1, gb + 8);
    };

    const int wm = warp >> 2, wn = warp & 3;
    const int lrow = lane & 15, lsel = lane >> 4;

    uint32_t aBase[4], aCh[4][2];
    #pragma unroll
    for (int im = 0; im < 4; im++) {
        const int r = wm * 64 + im * 16 + lrow;
        aBase[im] = sbA + (uint32_t)(r * 64);
        const int x = (r >> 1) & 3;
        aCh[im][0] = (uint32_t)((lsel ^ x) << 4);
        aCh[im][1] = (uint32_t)(((2 + lsel) ^ x) << 4);
    }
    uint32_t bBase[2], bCh[2][2];
    #pragma unroll
    for (int ip = 0; ip < 2; ip++) {
        const int r = wn * 32 + ip * 16 + lrow;
        bBase[ip] = sbB + (uint32_t)(r * 64);
        const int x = (r >> 1) & 3;
        bCh[ip][0] = (uint32_t)((lsel ^ x) << 4);
        bCh[ip][1] = (uint32_t)(((2 + lsel) ^ x) << 4);
    }

    float acc[4][4][4];
    #pragma unroll
    for (int a = 0; a < 4; a++)
        #pragma unroll
        for (int b = 0; b < 4; b++)
            #pragma unroll
            for (int c = 0; c < 4; c++) acc[a][b][c] = 0.f;

    #pragma unroll
    for (int p = 0; p < NSTAGE - 1; p++) {
        if (p < nkt) issue(p, p);
        cp_commit();
    }

    int st = 0, pst = NSTAGE - 1;
    for (int kt = 0; kt < nkt; kt++) {
        cp_wait<NSTAGE - 2>();
        __syncthreads();
        if (kt + NSTAGE - 1 < nkt) issue(kt + NSTAGE - 1, pst);
        cp_commit();

        const uint32_t stO = (uint32_t)(st * STAGEB);
        #pragma unroll
        for (int kk = 0; kk < 2; kk++) {
            uint32_t af[4][4], bf[2][4];
            #pragma unroll
            for (int im = 0; im < 4; im++) ldm4(af[im], aBase[im] + stO + aCh[im][kk]);
            #pragma unroll
            for (int ip = 0; ip < 2; ip++) ldm4(bf[ip], bBase[ip] + stO + bCh[ip][kk]);
            #pragma unroll
            for (int im = 0; im < 4; im++)
                #pragma unroll
                for (int ip = 0; ip < 2; ip++) {
                    mma16816(acc[im][2*ip],   af[im], bf[ip][0], bf[ip][2]);
                    mma16816(acc[im][2*ip+1], af[im], bf[ip][1], bf[ip][3]);
                }
        }
        st  = (st  == NSTAGE - 1) ? 0 : st + 1;
        pst = (pst == NSTAGE - 1) ? 0 : pst + 1;
    }

    const int g = lane >> 2, tg = lane & 3;
    #pragma unroll
    for (int im = 0; im < 4; im++) {
        const int r0 = m0 + wm * 64 + im * 16 + g;
        #pragma unroll
        for (int in = 0; in < 4; in++) {
            const int c = n0 + wn * 32 + in * 8 + 2 * tg;
            float v0 = acc[im][in][0], v1 = acc[im][in][1];
            float v2 = acc[im][in][2], v3 = acc[im][in][3];
            if (MODE == 0) {
                *(float2*)&Cf[(long)r0 * ldc + c]       = make_float2(v0, v1);
                *(float2*)&Cf[(long)(r0 + 8) * ldc + c] = make_float2(v2, v3);
            } else {
                if (MODE == 2) {
                    const float2 fa = *(const float2*)&f[(long)r0 * HD + (c & (HD - 1))];
                    const float2 fb = *(const float2*)&f[(long)(r0 + 8) * HD + (c & (HD - 1))];
                    float t0 = v0 * fa.x - v1 * fa.y;
                    float t1 = v0 * fa.y + v1 * fa.x;
                    float t2 = v2 * fb.x - v3 * fb.y;
                    float t3 = v2 * fb.y + v3 * fb.x;
                    v0 = t0; v1 = t1; v2 = t2; v3 = t3;
                }
                *(__half2*)&Ch[(long)r0 * ldc + c]       = __floats2half2_rn(v0, v1);
                *(__half2*)&Ch[(long)(r0 + 8) * ldc + c] = __floats2half2_rn(v2, v3);
            }
        }
    }
}

// ================= fused flash attention =================
// grid (16 row-blocks, 32 heads), 256 threads. Each warp owns 16 Q rows.
// Smem tiles [128 rows][128 halves], 256B rows of 16 chunks; phys chunk = c ^ (row&7).
__global__ void __launch_bounds__(256)
flash_attn(const __half* __restrict__ qh, const __half* __restrict__ kh,
           const __half* __restrict__ vh, __half* __restrict__ attnh)
{
    extern __shared__ char smem[];
    const int tid = threadIdx.x, lane = tid & 31, warp = tid >> 5;
    const int rb   = 15 - blockIdx.x;           // heavy blocks first
    const int head = blockIdx.y, kvh = head >> 2;
    const float rs = 0.08838834764831845f;

    const uint32_t sb = smem_u32(smem);
    const uint32_t sQ = sb, sK = sb + 32768u, sV = sb + 98304u;

    // producer mapping: row pr = tid>>1, chunks pc0..pc0+7
    const int pr = tid >> 1, pc0 = (tid & 1) * 8;
    uint32_t sOff[8];
    #pragma unroll
    for (int q = 0; q < 8; q++)
        sOff[q] = (uint32_t)(pr * 256 + (((pc0 + q) ^ (pr & 7)) << 4));

    const __half* qg = qh + (long)(rb * 128 + pr) * DIM + head * HD + pc0 * 8;
    const __half* kg = kh + (long)pr * KVDIM + kvh * HD + pc0 * 8;
    const __half* vg = vh + (long)pr * KVDIM + kvh * HD + pc0 * 8;

    auto issueKV = [&](const __half* g, uint32_t base, int tok0) {
        const __half* gp = g + (long)tok0 * KVDIM;
        #pragma unroll
        for (int q = 0; q < 8; q++) cp16(base + sOff[q], gp + q * 8);
    };

    #pragma unroll
    for (int q = 0; q < 8; q++) cp16(sQ + sOff[q], qg + q * 8);
    issueKV(kg, sK, 0); cp_commit();            // group [Q, K0]
    issueKV(vg, sV, 0); cp_commit();            // group [V0]

    const int wr = warp * 16, lrow = lane & 15, lsel = lane >> 4;
    const int g = lane >> 2, tg = lane & 3;

    cp_wait<1>(); __syncthreads();              // Q + K0 ready

    // Q fragments (warp rows wr..wr+15, 8 k16-tiles)
    uint32_t qf[8][4];
    {
        const int r = wr + lrow;
        const uint32_t qb = sQ + (uint32_t)(r * 256);
        const int x = r & 7;
        #pragma unroll
        for (int kt = 0; kt < 8; kt++)
            ldm4(qf[kt], qb + (uint32_t)(((2 * kt + lsel) ^ x) << 4));
    }

    float oacc[16][4];
    #pragma unroll
    for (int nt = 0; nt < 16; nt++)
        #pragma unroll
        for (int e = 0; e < 4; e++) oacc[nt][e] = 0.f;
    float m1 = -1e30f, m2 = -1e30f, l1 = 0.f, l2 = 0.f;

    const int grow1 = rb * 128 + wr + g;       // thread's global rows
    const int grow2 = grow1 + 8;

    for (int j = 0; j <= rb; j++) {
        if (j > 0) { cp_wait<1>(); __syncthreads(); }
        const uint32_t Kb = sK + (uint32_t)((j & 1) * 32768);
        const uint32_t Vb = sV + (uint32_t)((j & 1) * 32768);

        // ---- S = Q @ K^T ----
        float sacc[16][4];
        #pragma unroll
        for (int nt = 0; nt < 16; nt++)
            #pragma unroll
            for (int e = 0; e < 4; e++) sacc[nt][e] = 0.f;

        #pragma unroll
        for (int kt = 0; kt < 8; kt++) {
            #pragma unroll
            for (int ng = 0; ng < 8; ng++) {
                const int r = ng * 16 + lrow;
                uint32_t kb[4];
                ldm4(kb, Kb + (uint32_t)(r * 256) +
                         (uint32_t)((((2 * kt + lsel)) ^ (r & 7)) << 4));
                mma16816(sacc[2 * ng],     qf[kt], kb[0], kb[2]);
                mma16816(sacc[2 * ng + 1], qf[kt], kb[1], kb[3]);
            }
        }

        // ---- scale + causal mask (diag block only) ----
        #pragma unroll
        for (int nt = 0; nt < 16; nt++)
            #pragma unroll
            for (int e = 0; e < 4; e++) sacc[nt][e] *= rs;
        if (j == rb) {
            #pragma unroll
            for (int nt = 0; nt < 16; nt++) {
                const int c = j * 128 + nt * 8 + 2 * tg;
                if (c     > grow1) sacc[nt][0] = -1e30f;
                if (c + 1 > grow1) sacc[nt][1] = -1e30f;
                if (c     > grow2) sacc[nt][2] = -1e30f;
                if (c + 1 > grow2) sacc[nt][3] = -1e30f;
            }
        }

        // ---- online softmax ----
        float mx1 = -1e30f, mx2 = -1e30f;
        #pragma unroll
        for (int nt = 0; nt < 16; nt++) {
            mx1 = fmaxf(mx1, fmaxf(sacc[nt][0], sacc[nt][1]));
            mx2 = fmaxf(mx2, fmaxf(sacc[nt][2], sacc[nt][3]));
        }
        mx1 = fmaxf(mx1, __shfl_xor_sync(0xffffffffu, mx1, 1));
        mx1 = fmaxf(mx1, __shfl_xor_sync(0xffffffffu, mx1, 2));
        mx2 = fmaxf(mx2, __shfl_xor_sync(0xffffffffu, mx2, 1));
        mx2 = fmaxf(mx2, __shfl_xor_sync(0xffffffffu, mx2, 2));

        const float m1n = fmaxf(m1, mx1), m2n = fmaxf(m2, mx2);
        const float a1 = __expf(m1 - m1n), a2 = __expf(m2 - m2n);
        m1 = m1n; m2 = m2n;

        float s1 = 0.f, s2 = 0.f;
        #pragma unroll
        for (int nt = 0; nt < 16; nt++) {
            sacc[nt][0] = __expf(sacc[nt][0] - m1n);
            sacc[nt][1] = __expf(sacc[nt][1] - m1n);
            sacc[nt][2] = __expf(sacc[nt][2] - m2n);
            sacc[nt][3] = __expf(sacc[nt][3] - m2n);
            s1 += sacc[nt][0] + sacc[nt][1];
            s2 += sacc[nt][2] + sacc[nt][3];
        }
        s1 += __shfl_xor_sync(0xffffffffu, s1, 1);
        s1 += __shfl_xor_sync(0xffffffffu, s1, 2);
        s2 += __shfl_xor_sync(0xffffffffu, s2, 1);
        s2 += __shfl_xor_sync(0xffffffffu, s2, 2);
        l1 = l1 * a1 + s1;
        l2 = l2 * a2 + s2;

        #pragma unroll
        for (int nt = 0; nt < 16; nt++) {
            oacc[nt][0] *= a1; oacc[nt][1] *= a1;
            oacc[nt][2] *= a2; oacc[nt][3] *= a2;
        }

        cp_wait<0>(); __syncthreads();          // V_j ready

        // ---- O += P @ V ----
        #pragma unroll
        for (int kt2 = 0; kt2 < 8; kt2++) {
            uint32_t ph[4];
            ph[0] = pack_h2(sacc[2*kt2][0],   sacc[2*kt2][1]);
            ph[1] = pack_h2(sacc[2*kt2][2],   sacc[2*kt2][3]);
            ph[2] = pack_h2(sacc[2*kt2+1][0], sacc[2*kt2+1][1]);
            ph[3] = pack_h2(sacc[2*kt2+1][2], sacc[2*kt2+1][3]);
            const int tl = lane >> 3;
            const int krow = kt2 * 16 + (tl & 1) * 8 + (lane & 7);
            const uint32_t vrow = Vb + (uint32_t)(krow * 256);
            const int xk = krow & 7;
            #pragma unroll
            for (int ng = 0; ng < 8; ng++) {
                uint32_t vb[4];
                ldm4t(vb, vrow + (uint32_t)(((ng * 2 + (tl >> 1)) ^ xk) << 4));
                mma16816(oacc[2 * ng],     ph, vb[0], vb[1]);
                mma16816(oacc[2 * ng + 1], ph, vb[2], vb[3]);
            }
        }

        if (j < rb) {
            const uint32_t nb = (uint32_t)(((j + 1) & 1) * 32768);
            issueKV(kg, sK + nb, (j + 1) * 128); cp_commit();
            issueKV(vg, sV + nb, (j + 1) * 128); cp_commit();
        }
    }

    // ---- epilogue: O /= l, write half ----
    const float inv1 = 1.0f / l1, inv2 = 1.0f / l2;
    __half* o1 = attnh + (long)grow1 * DIM + head * HD;
    __half* o2 = attnh + (long)grow2 * DIM + head * HD;
    #pragma unroll
    for (int nt = 0; nt < 16; nt++) {
        const int c = nt * 8 + 2 * tg;
        *(__half2*)&o1[c] = __floats2half2_rn(oacc[nt][0] * inv1, oacc[nt][1] * inv1);
        *(__half2*)&o2[c] = __floats2half2_rn(oacc[nt][2] * inv2, oacc[nt][3] * inv2);
    }
}

// ================= helpers =================
__global__ void conv_h(const float4* __restrict__ in, __half2* __restrict__ out, long n4)
{
    long i = (long)blockIdx.x * blockDim.x + threadIdx.x;
    if (i >= n4) return;
    float4 v = in[i];
    out[2 * i]     = __floats2half2_rn(v.x, v.y);
    out[2 * i + 1] = __floats2half2_rn(v.z, v.w);
}

__global__ void transpose_fh(const float* __restrict__ in, __half* __restrict__ out,
                             int R, int C)
{
    __shared__ float t[32][33];
    const int bx = blockIdx.x * 32, by = blockIdx.y * 32;
    const int x = bx + threadIdx.x;
    #pragma unroll
    for (int j = 0; j < 32; j += 8)
        t[threadIdx.y + j][threadIdx.x] = in[(long)(by + threadIdx.y + j) * C + x];
    __syncthreads();
    const int x2 = by + threadIdx.x;
    #pragma unroll
    for (int j = 0; j < 32; j += 8)
        out[(long)(bx + threadIdx.y + j) * R + x2] =
            __float2half_rn(t[threadIdx.x][threadIdx.y + j]);
}

extern "C" void kernel_launch(void* const* d_in, const int* in_sizes, int n_in,
                              void* d_out, int out_size)
{
    const float* x  = (const float*)d_in[0];
    // d_in[1] = cache_kv (unused: start_pos=0, L=SEQ)
    const float* fr = (const float*)d_in[2];
    const float* wq = (const float*)d_in[3];
    const float* wk = (const float*)d_in[4];
    const float* wv = (const float*)d_in[5];
    const float* wo = (const float*)d_in[6];
    float* out = (float*)d_out;

    __half *xh, *wqT, *wkT, *wvT, *woT, *qh, *kh, *vh, *attnh;
    cudaGetSymbolAddress((void**)&xh,   g_xh);
    cudaGetSymbolAddress((void**)&wqT,  g_wqT);
    cudaGetSymbolAddress((void**)&wkT,  g_wkT);
    cudaGetSymbolAddress((void**)&wvT,  g_wvT);
    cudaGetSymbolAddress((void**)&woT,  g_woT);
    cudaGetSymbolAddress((void**)&qh,   g_qh);
    cudaGetSymbolAddress((void**)&kh,   g_kh);
    cudaGetSymbolAddress((void**)&vh,   g_vh);
    cudaGetSymbolAddress((void**)&attnh,g_attnh);

    cudaFuncSetAttribute(gemm_h<0>, cudaFuncAttributeMaxDynamicSharedMemorySize, GSMEM);
    cudaFuncSetAttribute(gemm_h<1>, cudaFuncAttributeMaxDynamicSharedMemorySize, GSMEM);
    cudaFuncSetAttribute(gemm_h<2>, cudaFuncAttributeMaxDynamicSharedMemorySize, GSMEM);
    cudaFuncSetAttribute(flash_attn, cudaFuncAttributeMaxDynamicSharedMemorySize, FSMEM);

    dim3 tb(32, 8);
    {
        long n4 = (long)SEQ * DIM / 4;
        conv_h<<<(n4 + 255) / 256, 256>>>((const float4*)x, (__half2*)xh, n4);
    }
    transpose_fh<<<dim3(DIM / 32,   DIM / 32), tb>>>(wq, wqT, DIM, DIM);
    transpose_fh<<<dim3(KVDIM / 32, DIM / 32), tb>>>(wk, wkT, DIM, KVDIM);
    transpose_fh<<<dim3(KVDIM / 32, DIM / 32), tb>>>(wv, wvT, DIM, KVDIM);
    transpose_fh<<<dim3(DIM / 32,   DIM / 32), tb>>>(wo, woT, DIM, DIM);

    // Projections. Q/K fuse RoPE (MODE 2); V plain half (MODE 1).
    gemm_h<2><<<dim3(DIM / BNT,   SEQ / BMT), 256, GSMEM>>>(
        xh, wqT, nullptr, qh, fr, DIM, DIM, DIM, DIM);
    gemm_h<2><<<dim3(KVDIM / BNT, SEQ / BMT), 256, GSMEM>>>(
        xh, wkT, nullptr, kh, fr, DIM, DIM, DIM, KVDIM);
    gemm_h<1><<<dim3(KVDIM / BNT, SEQ / BMT), 256, GSMEM>>>(
        xh, wvT, nullptr, vh, nullptr, DIM, DIM, DIM, KVDIM);

    // Fused attention: scores + softmax + PV
    flash_attn<<<dim3(16, NHEADS), 256, FSMEM>>>(qh, kh, vh, attnh);

    // out = attn @ wo, fp32 out
    gemm_h<0><<<dim3(DIM / BNT, SEQ / BMT), 256, GSMEM>>>(
        attnh, woT, out, nullptr, nullptr, DIM, DIM, DIM, DIM);
}